// round 5
// baseline (speedup 1.0000x reference)
#include <cuda_runtime.h>
#include <cuda_bf16.h>

// ConvSpatialPropagationNet_71949292143069
//
// Math (verified on HW in R1, rel_err 6.1e-8): the reference's propagation
// multiplies the padded gate tensor by the padded depth ELEMENTWISE (no
// neighbor gather), so each step is d <- (1-G)*raw + G*d with d0 = raw,
// whose fixed point is d = raw = blur_depth. Output = copy of d_in[1].
//
// Round history:
//   R1: 3344 CTAs, MLP=1, plain ops      -> 6.66 us, DRAM 25.4%, occ 77%
//   R4:  836 CTAs, MLP=4, .cs hints      -> 7.23 us, DRAM 24.2%, occ 51%  (REGRESSION)
// Lesson: for a tiny streaming copy, chip-level parallelism (resident warps)
// matters more than per-thread MLP; .cs also forfeits L2 hits on the
// graph-replay-resident input. R5: MLP=2, 1672 CTAs, no cache hints.
// Each block moves a contiguous 8 KB tile (512 float4);
// N4 = 856,064 = 1672 * 512 exactly (no tail, predicates uniformly true).

__global__ void __launch_bounds__(256)
cspn_copy2_kernel(const float4* __restrict__ in,
                  float4* __restrict__ out,
                  int n4) {
    int base = blockIdx.x * 512 + threadIdx.x;
    int i0 = base;
    int i1 = base + 256;

    float4 a, b;
    bool p0 = i0 < n4;
    bool p1 = i1 < n4;

    if (p0) a = in[i0];
    if (p1) b = in[i1];

    if (p0) out[i0] = a;
    if (p1) out[i1] = b;
}

extern "C" void kernel_launch(void* const* d_in, const int* in_sizes, int n_in,
                              void* d_out, int out_size) {
    // Inputs (metadata order): guidance, blur_depth, sparse_depth, sum_w
    const float* blur_depth = (const float*)d_in[1];
    float* out = (float*)d_out;

    int n  = in_sizes[1];              // 3,424,256
    int n4 = n >> 2;                   // 856,064 float4
    int per_block = 512;               // float4 per block (8 KB)
    int blocks = (n4 + per_block - 1) / per_block;   // 1672

    cspn_copy2_kernel<<<blocks, 256>>>((const float4*)blur_depth,
                                       (float4*)out, n4);
}